// round 7
// baseline (speedup 1.0000x reference)
#include <cuda_runtime.h>
#include <math.h>

// ---------------- problem constants ----------------
#define D1   4096
#define D2   4096
#define C    16
#define N1   (D2 * C)        // 65536 columns of W1
#define KSPLIT 8
#define KTILE  (D1 / KSPLIT) // 512 rows per split
#define CTILE  128           // threads per gemv block
#define VEC    4             // floats per thread per row-step
#define CPT    (CTILE * VEC) // 512 columns per gemv block
#define ROWS_PT (KTILE / CTILE) // 4 a0-rows computed per gemv thread
#define NB2    128           // blocks in k_dan1 (32 threads each)

// ---------------- device scratch (no allocation allowed) ----------------
__device__ float g_a0[D1];                 // layer-0 activations (== a0_copy)
__device__ float g_part[KSPLIT * N1];      // split-K partial sums (2 MB)
__device__ float g_h2p[NB2 * C];           // per-block layer-2 partials
__device__ unsigned int g_ctr = 0;         // last-block-done counter (self-resets)

// ---------------- shared tiny DAN: 16(+code) -> 15 -> 8 -> 1, tanh ----------------
__device__ __forceinline__ float dan_tanh(
    const float* z, int layer,
    const float* __restrict__ Wd1, const float* __restrict__ bd1,
    const float* __restrict__ Wd2, const float* __restrict__ bd2,
    const float* __restrict__ Wd3, const float* __restrict__ bd3)
{
    // one-hot layer code == row (C+layer) of Wd1 folded in as extra bias
    float h1[15];
#pragma unroll
    for (int j = 0; j < 15; ++j) {
        float v = bd1[j] + Wd1[(C + layer) * 15 + j];
#pragma unroll
        for (int c = 0; c < C; ++c)
            v = fmaf(z[c], Wd1[c * 15 + j], v);
        h1[j] = v > 0.f ? v : 0.01f * v;     // leaky_relu(0.01)
    }
    float h2[8];
#pragma unroll
    for (int j = 0; j < 8; ++j) {
        float v = bd2[j];
#pragma unroll
        for (int i = 0; i < 15; ++i)
            v = fmaf(h1[i], Wd2[i * 8 + j], v);
        h2[j] = v > 0.f ? v : 0.01f * v;
    }
    float o = bd3[0];
#pragma unroll
    for (int i = 0; i < 8; ++i)
        o = fmaf(h2[i], Wd3[i], o);
    return tanhf(o);
}

// ---------------- kernel B: fused layer0 + big GEMV ----------------
// grid = (N1/CPT, KSPLIT) = (128, 8) blocks of 128 threads.
// Each block recomputes its own a0[k0..k0+KTILE) slice (identical fp sequence
// in every block -> deterministic), then streams its W1 panel.
// blockIdx.x==0 blocks persist the slice to g_a0 for the skip connection.
__global__ void __launch_bounds__(CTILE) k_gemv(
    const float* __restrict__ x,
    const float* __restrict__ W0, const float* __restrict__ b0,
    const float* __restrict__ W1,
    const float* __restrict__ Wd1, const float* __restrict__ bd1,
    const float* __restrict__ Wd2, const float* __restrict__ bd2,
    const float* __restrict__ Wd3, const float* __restrict__ bd3)
{
    __shared__ float s[KTILE];
    const int t  = threadIdx.x;
    const int k0 = blockIdx.y * KTILE;
    const float xv = x[0];

    // ---- compute a0 slice for this K-split (layer 0) ----
#pragma unroll
    for (int i = 0; i < ROWS_PT; ++i) {
        const int j = k0 + i * CTILE + t;
        float z[C];
        const float4* w4 = reinterpret_cast<const float4*>(W0 + (size_t)j * C);
        const float4* b4 = reinterpret_cast<const float4*>(b0 + (size_t)j * C);
#pragma unroll
        for (int q = 0; q < 4; ++q) {
            float4 w = w4[q], b = b4[q];
            z[4 * q + 0] = fmaf(xv, w.x, b.x);
            z[4 * q + 1] = fmaf(xv, w.y, b.y);
            z[4 * q + 2] = fmaf(xv, w.z, b.z);
            z[4 * q + 3] = fmaf(xv, w.w, b.w);
        }
        float a = dan_tanh(z, 0, Wd1, bd1, Wd2, bd2, Wd3, bd3);
        s[i * CTILE + t] = a;
        if (blockIdx.x == 0)
            g_a0[j] = a;
    }
    __syncthreads();

    // ---- stream the W1 panel ----
    const int col4 = blockIdx.x * CPT + t * VEC;
    const float4* __restrict__ w =
        reinterpret_cast<const float4*>(W1 + (size_t)k0 * N1 + col4);
    const size_t rowstep = N1 / VEC;

    float4 acc = make_float4(0.f, 0.f, 0.f, 0.f);
#pragma unroll 8
    for (int kk = 0; kk < KTILE; ++kk) {
        float4 wv = __ldcs(&w[(size_t)kk * rowstep]);  // stream, don't pollute L2
        float  a  = s[kk];
        acc.x = fmaf(a, wv.x, acc.x);
        acc.y = fmaf(a, wv.y, acc.y);
        acc.z = fmaf(a, wv.z, acc.z);
        acc.w = fmaf(a, wv.w, acc.w);
    }
    *reinterpret_cast<float4*>(&g_part[(size_t)blockIdx.y * N1 + col4]) = acc;
}

// ---------------- kernel C: reduce + skip + DAN1 + fused layer-2 + final DAN ----------------
// 128 blocks x 32 threads (1 warp); one row j per thread, float4 loads,
// warp-shfl reduction of the 16 layer-2 channels. The LAST block to finish
// reduces the 128 partials and emits the final scalar (fixed-order sum ->
// deterministic).
__global__ void __launch_bounds__(32) k_dan1(
    const float* __restrict__ x,
    const float* __restrict__ b1,
    const float* __restrict__ Ws02, const float* __restrict__ bs02,
    const float* __restrict__ W2,   const float* __restrict__ Ws13,
    const float* __restrict__ b2,   const float* __restrict__ bs13,
    const float* __restrict__ Wd1, const float* __restrict__ bd1,
    const float* __restrict__ Wd2, const float* __restrict__ bd2,
    const float* __restrict__ Wd3, const float* __restrict__ bd3,
    float* __restrict__ out)
{
    __shared__ float zsh[C];
    __shared__ bool  isLast;
    const int t = threadIdx.x;
    const int j = blockIdx.x * 32 + t;
    const float xv = x[0];

    // gather the 16 pre-activations for row j, all as float4
    float z[C];
    {
        const float4* b4  = reinterpret_cast<const float4*>(b1   + (size_t)j * C);
        const float4* w4  = reinterpret_cast<const float4*>(Ws02 + (size_t)j * C);
        const float4* sb4 = reinterpret_cast<const float4*>(bs02 + (size_t)j * C);
#pragma unroll
        for (int q = 0; q < 4; ++q) {
            float4 b = b4[q], w = w4[q], sb = sb4[q];
            z[4 * q + 0] = b.x + fmaf(xv, w.x, sb.x);
            z[4 * q + 1] = b.y + fmaf(xv, w.y, sb.y);
            z[4 * q + 2] = b.z + fmaf(xv, w.z, sb.z);
            z[4 * q + 3] = b.w + fmaf(xv, w.w, sb.w);
        }
#pragma unroll
        for (int sp = 0; sp < KSPLIT; ++sp) {
            const float4* p4 =
                reinterpret_cast<const float4*>(&g_part[(size_t)sp * N1 + (size_t)j * C]);
#pragma unroll
            for (int q = 0; q < 4; ++q) {
                float4 p = p4[q];
                z[4 * q + 0] += p.x;
                z[4 * q + 1] += p.y;
                z[4 * q + 2] += p.z;
                z[4 * q + 3] += p.w;
            }
        }
    }
    float a1 = dan_tanh(z, 1, Wd1, bd1, Wd2, bd2, Wd3, bd3);
    float a0 = g_a0[j];

    // layer-2 contribution of row j -> 16 channels in registers
    float v[C];
    {
        const float4* w2 = reinterpret_cast<const float4*>(W2   + (size_t)j * C);
        const float4* ws = reinterpret_cast<const float4*>(Ws13 + (size_t)j * C);
#pragma unroll
        for (int q = 0; q < 4; ++q) {
            float4 w = w2[q], sv = ws[q];
            v[4 * q + 0] = fmaf(a1, w.x, a0 * sv.x);
            v[4 * q + 1] = fmaf(a1, w.y, a0 * sv.y);
            v[4 * q + 2] = fmaf(a1, w.z, a0 * sv.z);
            v[4 * q + 3] = fmaf(a1, w.w, a0 * sv.w);
        }
    }
    // warp-shfl tree reduce (fixed order -> deterministic)
#pragma unroll
    for (int st = 16; st >= 1; st >>= 1) {
#pragma unroll
        for (int c = 0; c < C; ++c)
            v[c] += __shfl_down_sync(0xffffffffu, v[c], st);
    }
    if (t == 0) {
#pragma unroll
        for (int c = 0; c < C; ++c)
            g_h2p[blockIdx.x * C + c] = v[c];
    }

    // ---- last-block-done: reduce the 128 partials + final DAN ----
    __threadfence();
    if (t == 0) {
        unsigned int old = atomicAdd(&g_ctr, 1u);
        isLast = (old == NB2 - 1);
        if (isLast) g_ctr = 0;     // self-reset for next graph replay
    }
    __syncwarp();
    __syncthreads();
    if (!isLast) return;

    if (t < C) {
        float acc = b2[t] + bs13[t];
#pragma unroll 8
        for (int b = 0; b < NB2; ++b)
            acc += g_h2p[b * C + t];
        zsh[t] = acc;
    }
    __syncwarp();
    if (t == 0) {
        float zf[C];
#pragma unroll
        for (int c = 0; c < C; ++c) zf[c] = zsh[c];
        out[0] = dan_tanh(zf, 2, Wd1, bd1, Wd2, bd2, Wd3, bd3);
    }
}

// ---------------- launch ----------------
extern "C" void kernel_launch(void* const* d_in, const int* in_sizes, int n_in,
                              void* d_out, int out_size)
{
    const float* x    = (const float*)d_in[0];
    const float* W0   = (const float*)d_in[1];
    const float* b0   = (const float*)d_in[2];
    const float* W1   = (const float*)d_in[3];
    const float* b1   = (const float*)d_in[4];
    const float* W2   = (const float*)d_in[5];
    const float* b2   = (const float*)d_in[6];
    const float* Ws02 = (const float*)d_in[7];
    const float* bs02 = (const float*)d_in[8];
    const float* Ws13 = (const float*)d_in[9];
    const float* bs13 = (const float*)d_in[10];
    const float* Wd1  = (const float*)d_in[11];
    const float* bd1  = (const float*)d_in[12];
    const float* Wd2  = (const float*)d_in[13];
    const float* bd2  = (const float*)d_in[14];
    const float* Wd3  = (const float*)d_in[15];
    const float* bd3  = (const float*)d_in[16];
    float* out = (float*)d_out;

    // fused layer0 + big GEMV (split-K, float4 streaming loads)
    dim3 gg(N1 / CPT, KSPLIT);
    k_gemv<<<gg, CTILE>>>(x, W0, b0, W1, Wd1, bd1, Wd2, bd2, Wd3, bd3);

    // reduce + skip + DAN layer 1 + fused layer-2 + final DAN (last block)
    k_dan1<<<NB2, 32>>>(x, b1, Ws02, bs02, W2, Ws13, b2, bs13,
                        Wd1, bd1, Wd2, bd2, Wd3, bd3, out);
}

// round 8
// speedup vs baseline: 1.3264x; 1.3264x over previous
#include <cuda_runtime.h>
#include <math.h>

// ---------------- problem constants ----------------
#define D1   4096
#define D2   4096
#define C    16
#define N1   (D2 * C)        // 65536 columns of W1
#define KSPLIT 16
#define KTILE  (D1 / KSPLIT) // 256 rows per split
#define CTILE  128           // threads per gemv block
#define VEC    4             // floats per thread per row-step
#define CPT    (CTILE * VEC) // 512 columns per gemv block
#define NB2    32            // blocks in k_dan1 (128 threads each)

// ---------------- device scratch (no allocation allowed) ----------------
__device__ float g_a0[D1];                 // layer-0 activations (== a0_copy)
__device__ float g_part[KSPLIT * N1];      // split-K partial sums (4 MB)
__device__ float g_h2p[NB2 * C];           // per-block layer-2 partials
__device__ unsigned int g_ctr = 0;         // last-block-done counter (self-resets)

// ---------------- shared tiny DAN: 16(+code) -> 15 -> 8 -> 1, tanh ----------------
__device__ __forceinline__ float dan_tanh(
    const float* z, int layer,
    const float* __restrict__ Wd1, const float* __restrict__ bd1,
    const float* __restrict__ Wd2, const float* __restrict__ bd2,
    const float* __restrict__ Wd3, const float* __restrict__ bd3)
{
    // one-hot layer code == row (C+layer) of Wd1 folded in as extra bias
    float h1[15];
#pragma unroll
    for (int j = 0; j < 15; ++j) {
        float v = bd1[j] + Wd1[(C + layer) * 15 + j];
#pragma unroll
        for (int c = 0; c < C; ++c)
            v = fmaf(z[c], Wd1[c * 15 + j], v);
        h1[j] = v > 0.f ? v : 0.01f * v;     // leaky_relu(0.01)
    }
    float h2[8];
#pragma unroll
    for (int j = 0; j < 8; ++j) {
        float v = bd2[j];
#pragma unroll
        for (int i = 0; i < 15; ++i)
            v = fmaf(h1[i], Wd2[i * 8 + j], v);
        h2[j] = v > 0.f ? v : 0.01f * v;
    }
    float o = bd3[0];
#pragma unroll
    for (int i = 0; i < 8; ++i)
        o = fmaf(h2[i], Wd3[i], o);
    return tanhf(o);
}

// ---------------- kernel A: layer 0 (x*W0+b0 -> DAN -> a0) ----------------
// 128 blocks x 32 threads: one row per thread, spread across 128 SMs so the
// latency chain (LDG.128 + ~400 FMA + tanh) is the wall, not SM count.
__global__ void __launch_bounds__(32) k_layer0(
    const float* __restrict__ x,
    const float* __restrict__ W0, const float* __restrict__ b0,
    const float* __restrict__ Wd1, const float* __restrict__ bd1,
    const float* __restrict__ Wd2, const float* __restrict__ bd2,
    const float* __restrict__ Wd3, const float* __restrict__ bd3)
{
    int j = blockIdx.x * 32 + threadIdx.x;
    float xv = x[0];
    float z[C];
    const float4* w4 = reinterpret_cast<const float4*>(W0 + (size_t)j * C);
    const float4* b4 = reinterpret_cast<const float4*>(b0 + (size_t)j * C);
#pragma unroll
    for (int q = 0; q < 4; ++q) {
        float4 w = w4[q], b = b4[q];
        z[4 * q + 0] = fmaf(xv, w.x, b.x);
        z[4 * q + 1] = fmaf(xv, w.y, b.y);
        z[4 * q + 2] = fmaf(xv, w.z, b.z);
        z[4 * q + 3] = fmaf(xv, w.w, b.w);
    }
    g_a0[j] = dan_tanh(z, 0, Wd1, bd1, Wd2, bd2, Wd3, bd3);
}

// ---------------- kernel B: big GEMV  a0[4096] @ W1[4096 x 65536], float4 ----------------
// grid = (N1/CPT, KSPLIT) = (128, 16) = 2048 blocks of 128 threads (better
// wave balance: ~13.8 blocks/SM). Deterministic split-K partials.
__global__ void __launch_bounds__(CTILE) k_gemv(const float* __restrict__ W1)
{
    __shared__ float s[KTILE];
    const int col4 = blockIdx.x * CPT + threadIdx.x * VEC;
    const int k0   = blockIdx.y * KTILE;

    for (int i = threadIdx.x; i < KTILE; i += CTILE)
        s[i] = g_a0[k0 + i];
    __syncthreads();

    const float4* __restrict__ w =
        reinterpret_cast<const float4*>(W1 + (size_t)k0 * N1 + col4);
    const size_t rowstep = N1 / VEC;

    float4 acc = make_float4(0.f, 0.f, 0.f, 0.f);
#pragma unroll 8
    for (int kk = 0; kk < KTILE; ++kk) {
        float4 wv = __ldcs(&w[(size_t)kk * rowstep]);  // stream, don't pollute L2
        float  a  = s[kk];
        acc.x = fmaf(a, wv.x, acc.x);
        acc.y = fmaf(a, wv.y, acc.y);
        acc.z = fmaf(a, wv.z, acc.z);
        acc.w = fmaf(a, wv.w, acc.w);
    }
    *reinterpret_cast<float4*>(&g_part[(size_t)blockIdx.y * N1 + col4]) = acc;
}

// ---------------- kernel C: reduce + skip + DAN1 + fused layer-2 + final DAN ----------------
// 32 blocks x 128 threads; one row j per thread, all loads float4.
// Per-block 16-wide partials -> g_h2p; the LAST block to finish reduces the
// 32 partials and emits the final scalar (deterministic: fixed-order sum).
__global__ void __launch_bounds__(128) k_dan1(
    const float* __restrict__ x,
    const float* __restrict__ b1,
    const float* __restrict__ Ws02, const float* __restrict__ bs02,
    const float* __restrict__ W2,   const float* __restrict__ Ws13,
    const float* __restrict__ b2,   const float* __restrict__ bs13,
    const float* __restrict__ Wd1, const float* __restrict__ bd1,
    const float* __restrict__ Wd2, const float* __restrict__ bd2,
    const float* __restrict__ Wd3, const float* __restrict__ bd3,
    float* __restrict__ out)
{
    __shared__ float red[C * 128];   // 8 KB, column-major: red[c*128 + t]
    __shared__ bool  isLast;
    const int t = threadIdx.x;
    const int j = blockIdx.x * 128 + t;
    const float xv = x[0];

    // gather the 16 pre-activations for row j, all as float4
    float z[C];
    {
        const float4* b4  = reinterpret_cast<const float4*>(b1   + (size_t)j * C);
        const float4* w4  = reinterpret_cast<const float4*>(Ws02 + (size_t)j * C);
        const float4* sb4 = reinterpret_cast<const float4*>(bs02 + (size_t)j * C);
#pragma unroll
        for (int q = 0; q < 4; ++q) {
            float4 b = b4[q], w = w4[q], sb = sb4[q];
            z[4 * q + 0] = b.x + fmaf(xv, w.x, sb.x);
            z[4 * q + 1] = b.y + fmaf(xv, w.y, sb.y);
            z[4 * q + 2] = b.z + fmaf(xv, w.z, sb.z);
            z[4 * q + 3] = b.w + fmaf(xv, w.w, sb.w);
        }
#pragma unroll
        for (int sp = 0; sp < KSPLIT; ++sp) {
            const float4* p4 =
                reinterpret_cast<const float4*>(&g_part[(size_t)sp * N1 + (size_t)j * C]);
#pragma unroll
            for (int q = 0; q < 4; ++q) {
                float4 p = p4[q];
                z[4 * q + 0] += p.x;
                z[4 * q + 1] += p.y;
                z[4 * q + 2] += p.z;
                z[4 * q + 3] += p.w;
            }
        }
    }
    float a1 = dan_tanh(z, 1, Wd1, bd1, Wd2, bd2, Wd3, bd3);
    float a0 = g_a0[j];

    // layer-2 contribution of row j
    const float4* w2 = reinterpret_cast<const float4*>(W2   + (size_t)j * C);
    const float4* ws = reinterpret_cast<const float4*>(Ws13 + (size_t)j * C);
#pragma unroll
    for (int q = 0; q < 4; ++q) {
        float4 w = w2[q], sv = ws[q];
        red[(4 * q + 0) * 128 + t] = fmaf(a1, w.x, a0 * sv.x);
        red[(4 * q + 1) * 128 + t] = fmaf(a1, w.y, a0 * sv.y);
        red[(4 * q + 2) * 128 + t] = fmaf(a1, w.z, a0 * sv.z);
        red[(4 * q + 3) * 128 + t] = fmaf(a1, w.w, a0 * sv.w);
    }
    __syncthreads();

    // tree reduce over the 128 threads for each of the 16 channels
#pragma unroll
    for (int st = 64; st >= 1; st >>= 1) {
        if (t < st) {
#pragma unroll
            for (int c = 0; c < C; ++c)
                red[c * 128 + t] += red[c * 128 + t + st];
        }
        __syncthreads();
    }
    if (t < C)
        g_h2p[blockIdx.x * C + t] = red[t * 128];

    // ---- last-block-done: reduce the 32 partials + final DAN ----
    __threadfence();
    if (t == 0) {
        unsigned int old = atomicAdd(&g_ctr, 1u);
        isLast = (old == NB2 - 1);
        if (isLast) g_ctr = 0;     // self-reset for next graph replay
    }
    __syncthreads();
    if (!isLast) return;

    if (t < C) {
        float v = b2[t] + bs13[t];
#pragma unroll
        for (int b = 0; b < NB2; ++b)
            v += g_h2p[b * C + t];
        red[t] = v;
    }
    __syncthreads();
    if (t == 0) {
        float zf[C];
#pragma unroll
        for (int c = 0; c < C; ++c) zf[c] = red[c];
        out[0] = dan_tanh(zf, 2, Wd1, bd1, Wd2, bd2, Wd3, bd3);
    }
}

// ---------------- launch ----------------
extern "C" void kernel_launch(void* const* d_in, const int* in_sizes, int n_in,
                              void* d_out, int out_size)
{
    const float* x    = (const float*)d_in[0];
    const float* W0   = (const float*)d_in[1];
    const float* b0   = (const float*)d_in[2];
    const float* W1   = (const float*)d_in[3];
    const float* b1   = (const float*)d_in[4];
    const float* W2   = (const float*)d_in[5];
    const float* b2   = (const float*)d_in[6];
    const float* Ws02 = (const float*)d_in[7];
    const float* bs02 = (const float*)d_in[8];
    const float* Ws13 = (const float*)d_in[9];
    const float* bs13 = (const float*)d_in[10];
    const float* Wd1  = (const float*)d_in[11];
    const float* bd1  = (const float*)d_in[12];
    const float* Wd2  = (const float*)d_in[13];
    const float* bd2  = (const float*)d_in[14];
    const float* Wd3  = (const float*)d_in[15];
    const float* bd3  = (const float*)d_in[16];
    float* out = (float*)d_out;

    // layer 0 -> a0 (wide SM spread, latency-bound)
    k_layer0<<<D1 / 32, 32>>>(x, W0, b0, Wd1, bd1, Wd2, bd2, Wd3, bd3);

    // big GEMV (split-K=16, float4 streaming loads, deterministic partials)
    dim3 gg(N1 / CPT, KSPLIT);
    k_gemv<<<gg, CTILE>>>(W1);

    // reduce + skip + DAN layer 1 + fused layer-2 + final DAN (last block)
    k_dan1<<<NB2, 128>>>(x, b1, Ws02, bs02, W2, Ws13, b2, bs13,
                         Wd1, bd1, Wd2, bd2, Wd3, bd3, out);
}